// round 1
// baseline (speedup 1.0000x reference)
#include <cuda_runtime.h>
#include <cuda_bf16.h>
#include <cstdint>

#define B_SZ    32
#define T_STEPS 200
#define E_DIM   32
#define H_DIM   128
#define V_DIM   8000
#define M_TOT   (B_SZ * T_STEPS)          // 6400 rows of hs
#define OUT_SEQ_ELEMS ((size_t)M_TOT * V_DIM)

// ---------------- scratch (no allocation allowed -> device globals) ----------
__device__ __align__(128) __nv_bfloat16 g_hs_hi[M_TOT * H_DIM];
__device__ __align__(128) __nv_bfloat16 g_hs_lo[M_TOT * H_DIM];
__device__ __align__(128) __nv_bfloat16 g_vw_hi[V_DIM * H_DIM];
__device__ __align__(128) __nv_bfloat16 g_vw_lo[V_DIM * H_DIM];

// ---------------- kernel 1: split Vw into bf16 hi + lo residual -------------
__global__ void split_vw_kernel(const float* __restrict__ Vw) {
    int i = blockIdx.x * 256 + threadIdx.x;
    if (i < V_DIM * H_DIM) {
        float v = Vw[i];
        __nv_bfloat16 h = __float2bfloat16(v);
        g_vw_hi[i] = h;
        g_vw_lo[i] = __float2bfloat16(v - __bfloat162float(h));
    }
}

// ---------------- kernel 2: recurrence (1 CTA per batch row) ----------------
// 512 threads: tid = j*4 + q. Thread (j,q) owns Ww[j][q*32 .. q*32+31] and
// Uw[j][q*8 .. q*8+7] in registers. h kept in smem, double buffered, chunk q
// stored at stride 40 floats so the 4 q-broadcast reads per warp hit 4
// distinct banks (conflict-free).
__global__ void __launch_bounds__(512) rnn_rec_kernel(
    const float* __restrict__ x,  const float* __restrict__ Ww,
    const float* __restrict__ Wb, const float* __restrict__ Uw,
    const float* __restrict__ Ub, float* __restrict__ hidden_out)
{
    __shared__ __align__(16) float xs[T_STEPS * E_DIM];   // 25.6 KB
    __shared__ __align__(16) float hbuf[2][160];          // 4 chunks * stride 40

    const int b   = blockIdx.x;
    const int tid = threadIdx.x;
    const int j   = tid >> 2;
    const int q   = tid & 3;

    // whole x[b] into smem once
    const float* xb = x + (size_t)b * T_STEPS * E_DIM;
    for (int i = tid; i < T_STEPS * E_DIM; i += 512) xs[i] = xb[i];
    if (tid < 160) hbuf[0][tid] = 0.0f;

    // weights -> registers
    float wreg[32];
    {
        const float4* wr = (const float4*)(Ww + j * H_DIM + q * 32);
        #pragma unroll
        for (int i = 0; i < 8; i++) {
            float4 v = wr[i];
            wreg[4*i+0] = v.x; wreg[4*i+1] = v.y;
            wreg[4*i+2] = v.z; wreg[4*i+3] = v.w;
        }
    }
    float ureg[8];
    {
        const float4* ur = (const float4*)(Uw + j * E_DIM + q * 8);
        float4 v0 = ur[0], v1 = ur[1];
        ureg[0] = v0.x; ureg[1] = v0.y; ureg[2] = v0.z; ureg[3] = v0.w;
        ureg[4] = v1.x; ureg[5] = v1.y; ureg[6] = v1.z; ureg[7] = v1.w;
    }
    const float bias = Wb[j] + Ub[j];
    __syncthreads();

    const int hoff = q * 40;
    for (int t = 0; t < T_STEPS; t++) {
        const float4* hr = (const float4*)(&hbuf[t & 1][hoff]);
        float acc = 0.0f;
        #pragma unroll
        for (int k = 0; k < 8; k++) {
            float4 hv = hr[k];
            acc += wreg[4*k+0] * hv.x + wreg[4*k+1] * hv.y
                 + wreg[4*k+2] * hv.z + wreg[4*k+3] * hv.w;
        }
        const float4* xt = (const float4*)(&xs[t * E_DIM + q * 8]);
        {
            float4 x0 = xt[0], x1 = xt[1];
            acc += ureg[0]*x0.x + ureg[1]*x0.y + ureg[2]*x0.z + ureg[3]*x0.w;
            acc += ureg[4]*x1.x + ureg[5]*x1.y + ureg[6]*x1.z + ureg[7]*x1.w;
        }
        // reduce across the 4 q-lanes (lane bits 0..1)
        acc += __shfl_xor_sync(0xffffffffu, acc, 1);
        acc += __shfl_xor_sync(0xffffffffu, acc, 2);
        float hv = tanhf(acc + bias);

        if (q == 0) hbuf[(t + 1) & 1][(j >> 5) * 40 + (j & 31)] = hv;
        __nv_bfloat16 hi = __float2bfloat16(hv);
        size_t gi = ((size_t)b * T_STEPS + t) * H_DIM + j;
        if (q == 1) g_hs_hi[gi] = hi;
        if (q == 2) g_hs_lo[gi] = __float2bfloat16(hv - __bfloat162float(hi));
        if (q == 3 && t == T_STEPS - 1) hidden_out[b * H_DIM + j] = hv;
        __syncthreads();
    }
}

// ---------------- kernel 3: output GEMM (split-bf16, mma.sync) --------------
// C[6400, 8000] = hs[6400,128] @ Vw[8000,128]^T + Vb
// CTA tile 128x128, full K=128 in one pass. 8 warps as 2(M)x4(N):
// warp tile 64x32, m16n8k16, acc fp32. hi*hi + hi*lo + lo*hi.
#define LDA 152   // bf16 elems/row: 304B rows -> conflict-free ldmatrix, 16B aligned
#define GEMM_SMEM (4 * 128 * LDA * (int)sizeof(__nv_bfloat16))  // 155648 B

#define MMA_BF16(C, A, Bf) asm volatile( \
    "mma.sync.aligned.m16n8k16.row.col.f32.bf16.bf16.f32 " \
    "{%0,%1,%2,%3}, {%4,%5,%6,%7}, {%8,%9}, {%0,%1,%2,%3};" \
    : "+f"((C)[0]), "+f"((C)[1]), "+f"((C)[2]), "+f"((C)[3]) \
    : "r"((A)[0]), "r"((A)[1]), "r"((A)[2]), "r"((A)[3]), \
      "r"((Bf)[0]), "r"((Bf)[1]))

__global__ void __launch_bounds__(256) out_gemm_kernel(
    const float* __restrict__ Vb, float* __restrict__ out)
{
    extern __shared__ __nv_bfloat16 sm[];
    __nv_bfloat16* As_hi = sm;
    __nv_bfloat16* As_lo = sm + 1 * 128 * LDA;
    __nv_bfloat16* Bs_hi = sm + 2 * 128 * LDA;
    __nv_bfloat16* Bs_lo = sm + 3 * 128 * LDA;

    const int tid = threadIdx.x;
    const int m0 = blockIdx.y * 128;
    const int n0 = blockIdx.x * 128;

    // cooperative tile load: 16B per access, rows 16B-aligned (LDA*2 = 304 % 16 == 0)
    {
        const int r0 = tid >> 4;
        const int c  = (tid & 15) * 8;
        #pragma unroll
        for (int i = 0; i < 8; i++) {
            int row = r0 + i * 16;
            *(uint4*)&As_hi[row * LDA + c] =
                *(const uint4*)&g_hs_hi[(size_t)(m0 + row) * H_DIM + c];
            *(uint4*)&As_lo[row * LDA + c] =
                *(const uint4*)&g_hs_lo[(size_t)(m0 + row) * H_DIM + c];
            int brow = n0 + row;
            uint4 wh = make_uint4(0, 0, 0, 0), wl = make_uint4(0, 0, 0, 0);
            if (brow < V_DIM) {
                wh = *(const uint4*)&g_vw_hi[(size_t)brow * H_DIM + c];
                wl = *(const uint4*)&g_vw_lo[(size_t)brow * H_DIM + c];
            }
            *(uint4*)&Bs_hi[row * LDA + c] = wh;
            *(uint4*)&Bs_lo[row * LDA + c] = wl;
        }
    }
    __syncthreads();

    const int w    = tid >> 5;
    const int lane = tid & 31;
    const int wm = (w >> 2) * 64;   // 0 or 64
    const int wn = (w & 3) * 32;    // 0,32,64,96

    float acc[4][4][4];
    #pragma unroll
    for (int i = 0; i < 4; i++)
        #pragma unroll
        for (int jj = 0; jj < 4; jj++)
            #pragma unroll
            for (int k = 0; k < 4; k++) acc[i][jj][k] = 0.0f;

    const int a_rl  = lane & 15;          // row within 16
    const int a_co  = (lane >> 4) * 8;    // col offset 0/8
    const int b_rl  = lane & 7;
    const int b_co  = lane & 8;

    #pragma unroll 1
    for (int kc = 0; kc < 8; kc++) {
        const int kb = kc * 16;
        unsigned ah[4][4], al[4][4];
        #pragma unroll
        for (int rb = 0; rb < 4; rb++) {
            unsigned adr = (unsigned)__cvta_generic_to_shared(
                &As_hi[(wm + rb * 16 + a_rl) * LDA + kb + a_co]);
            asm volatile("ldmatrix.sync.aligned.m8n8.x4.shared.b16 {%0,%1,%2,%3}, [%4];"
                : "=r"(ah[rb][0]), "=r"(ah[rb][1]), "=r"(ah[rb][2]), "=r"(ah[rb][3])
                : "r"(adr));
            adr = (unsigned)__cvta_generic_to_shared(
                &As_lo[(wm + rb * 16 + a_rl) * LDA + kb + a_co]);
            asm volatile("ldmatrix.sync.aligned.m8n8.x4.shared.b16 {%0,%1,%2,%3}, [%4];"
                : "=r"(al[rb][0]), "=r"(al[rb][1]), "=r"(al[rb][2]), "=r"(al[rb][3])
                : "r"(adr));
        }
        unsigned bh[4][2], bl[4][2];
        #pragma unroll
        for (int cb = 0; cb < 4; cb++) {
            unsigned adr = (unsigned)__cvta_generic_to_shared(
                &Bs_hi[(wn + cb * 8 + b_rl) * LDA + kb + b_co]);
            asm volatile("ldmatrix.sync.aligned.m8n8.x2.shared.b16 {%0,%1}, [%2];"
                : "=r"(bh[cb][0]), "=r"(bh[cb][1]) : "r"(adr));
            adr = (unsigned)__cvta_generic_to_shared(
                &Bs_lo[(wn + cb * 8 + b_rl) * LDA + kb + b_co]);
            asm volatile("ldmatrix.sync.aligned.m8n8.x2.shared.b16 {%0,%1}, [%2];"
                : "=r"(bl[cb][0]), "=r"(bl[cb][1]) : "r"(adr));
        }
        #pragma unroll
        for (int rb = 0; rb < 4; rb++)
            #pragma unroll
            for (int cb = 0; cb < 4; cb++) {
                MMA_BF16(acc[rb][cb], ah[rb], bh[cb]);
                MMA_BF16(acc[rb][cb], ah[rb], bl[cb]);
                MMA_BF16(acc[rb][cb], al[rb], bh[cb]);
            }
    }

    // epilogue: + Vb, store (rows always < 6400; guard cols)
    #pragma unroll
    for (int rb = 0; rb < 4; rb++) {
        int row = m0 + wm + rb * 16 + (lane >> 2);
        #pragma unroll
        for (int cb = 0; cb < 4; cb++) {
            int col = n0 + wn + cb * 8 + (lane & 3) * 2;
            if (col < V_DIM) {
                float2 bv = *(const float2*)&Vb[col];
                float2 o0, o1;
                o0.x = acc[rb][cb][0] + bv.x; o0.y = acc[rb][cb][1] + bv.y;
                o1.x = acc[rb][cb][2] + bv.x; o1.y = acc[rb][cb][3] + bv.y;
                *(float2*)&out[(size_t)row * V_DIM + col] = o0;
                *(float2*)&out[(size_t)(row + 8) * V_DIM + col] = o1;
            }
        }
    }
}

// ---------------- launch ----------------------------------------------------
extern "C" void kernel_launch(void* const* d_in, const int* in_sizes, int n_in,
                              void* d_out, int out_size) {
    const float* x  = (const float*)d_in[0];
    const float* Ww = (const float*)d_in[1];
    const float* Wb = (const float*)d_in[2];
    const float* Uw = (const float*)d_in[3];
    const float* Ub = (const float*)d_in[4];
    const float* Vw = (const float*)d_in[5];
    const float* Vb = (const float*)d_in[6];
    float* out = (float*)d_out;

    cudaFuncSetAttribute(out_gemm_kernel,
                         cudaFuncAttributeMaxDynamicSharedMemorySize, GEMM_SMEM);

    split_vw_kernel<<<(V_DIM * H_DIM + 255) / 256, 256>>>(Vw);
    rnn_rec_kernel<<<B_SZ, 512>>>(x, Ww, Wb, Uw, Ub, out + OUT_SEQ_ELEMS);
    out_gemm_kernel<<<dim3((V_DIM + 127) / 128, M_TOT / 128), 256, GEMM_SMEM>>>(Vb, out);
}

// round 3
// speedup vs baseline: 1.0957x; 1.0957x over previous
#include <cuda_runtime.h>
#include <cuda_bf16.h>
#include <cstdint>

#define B_SZ    32
#define T_STEPS 200
#define E_DIM   32
#define H_DIM   128
#define V_DIM   8000
#define M_TOT   (B_SZ * T_STEPS)          // 6400 rows of hs
#define OUT_SEQ_ELEMS ((size_t)M_TOT * V_DIM)

#define MB 50                              // m-tiles (6400/128)
#define NB 63                              // n-tiles (ceil 8000/128)
#define NT (MB * NB)                       // 3150 tiles
#define GRID_GEMM 148

// ---------------- scratch (no allocation allowed -> device globals) ----------
__device__ __align__(128) __nv_bfloat16 g_hs_hi[M_TOT * H_DIM];
__device__ __align__(128) __nv_bfloat16 g_hs_lo[M_TOT * H_DIM];
__device__ __align__(128) __nv_bfloat16 g_vw_hi[V_DIM * H_DIM];
__device__ __align__(128) __nv_bfloat16 g_vw_lo[V_DIM * H_DIM];

// ---------------- kernel 1: fused recurrence (blocks 0..31) + Vw split ------
__global__ void __launch_bounds__(512) rec_split_kernel(
    const float* __restrict__ x,  const float* __restrict__ Ww,
    const float* __restrict__ Wb, const float* __restrict__ Uw,
    const float* __restrict__ Ub, const float* __restrict__ Vw,
    float* __restrict__ hidden_out)
{
    __shared__ __align__(16) float xs[T_STEPS * E_DIM];   // 25.6 KB
    __shared__ __align__(16) float hbuf[2][160];          // 4 chunks * stride 40

    const int tid = threadIdx.x;

    if (blockIdx.x >= B_SZ) {
        // ---- Vw split on the other SMs ----
        const int nblk = gridDim.x - B_SZ;
        for (int i = (blockIdx.x - B_SZ) * 512 + tid; i < V_DIM * H_DIM;
             i += nblk * 512) {
            float v = Vw[i];
            __nv_bfloat16 h = __float2bfloat16(v);
            g_vw_hi[i] = h;
            g_vw_lo[i] = __float2bfloat16(v - __bfloat162float(h));
        }
        return;
    }

    const int b = blockIdx.x;
    const int j = tid >> 2;
    const int q = tid & 3;

    const float* xb = x + (size_t)b * T_STEPS * E_DIM;
    for (int i = tid; i < T_STEPS * E_DIM; i += 512) xs[i] = xb[i];
    if (tid < 160) hbuf[0][tid] = 0.0f;

    float wreg[32];
    {
        const float4* wr = (const float4*)(Ww + j * H_DIM + q * 32);
        #pragma unroll
        for (int i = 0; i < 8; i++) {
            float4 v = wr[i];
            wreg[4*i+0] = v.x; wreg[4*i+1] = v.y;
            wreg[4*i+2] = v.z; wreg[4*i+3] = v.w;
        }
    }
    float ureg[8];
    {
        const float4* ur = (const float4*)(Uw + j * E_DIM + q * 8);
        float4 v0 = ur[0], v1 = ur[1];
        ureg[0] = v0.x; ureg[1] = v0.y; ureg[2] = v0.z; ureg[3] = v0.w;
        ureg[4] = v1.x; ureg[5] = v1.y; ureg[6] = v1.z; ureg[7] = v1.w;
    }
    const float bias = Wb[j] + Ub[j];
    __syncthreads();

    const int hoff = q * 40;
    for (int t = 0; t < T_STEPS; t++) {
        const float4* hr = (const float4*)(&hbuf[t & 1][hoff]);
        float acc = 0.0f;
        #pragma unroll
        for (int k = 0; k < 8; k++) {
            float4 hv = hr[k];
            acc += wreg[4*k+0] * hv.x + wreg[4*k+1] * hv.y
                 + wreg[4*k+2] * hv.z + wreg[4*k+3] * hv.w;
        }
        const float4* xt = (const float4*)(&xs[t * E_DIM + q * 8]);
        {
            float4 x0 = xt[0], x1 = xt[1];
            acc += ureg[0]*x0.x + ureg[1]*x0.y + ureg[2]*x0.z + ureg[3]*x0.w;
            acc += ureg[4]*x1.x + ureg[5]*x1.y + ureg[6]*x1.z + ureg[7]*x1.w;
        }
        acc += __shfl_xor_sync(0xffffffffu, acc, 1);
        acc += __shfl_xor_sync(0xffffffffu, acc, 2);
        float hv = tanhf(acc + bias);

        if (q == 0) hbuf[(t + 1) & 1][(j >> 5) * 40 + (j & 31)] = hv;
        __nv_bfloat16 hi = __float2bfloat16(hv);
        size_t gi = ((size_t)b * T_STEPS + t) * H_DIM + j;
        if (q == 1) g_hs_hi[gi] = hi;
        if (q == 2) g_hs_lo[gi] = __float2bfloat16(hv - __bfloat162float(hi));
        if (q == 3 && t == T_STEPS - 1) hidden_out[b * H_DIM + j] = hv;
        __syncthreads();
    }
}

// ---------------- kernel 2: persistent split-bf16 GEMM (mma.sync) -----------
// C[6400,8000] = hs @ Vw^T + Vb. Tiles 128x128, n-major tile order:
// B (Vw) tile resident in smem, A (hs) tile streamed + double buffered via
// cp.async so loads overlap mma+epilogue of the previous tile.
#define LDA2 136                               // bf16/row: 272B, conflict-free
#define TILE_B (128 * LDA2 * 2)                // 34816 B per tile
#define GEMM_SMEM (6 * TILE_B + 1024)          // A hi/lo x2 + B hi/lo = 209920

#define MMA_BF16(C, A, Bf) asm volatile( \
    "mma.sync.aligned.m16n8k16.row.col.f32.bf16.bf16.f32 " \
    "{%0,%1,%2,%3}, {%4,%5,%6,%7}, {%8,%9}, {%0,%1,%2,%3};" \
    : "+f"((C)[0]), "+f"((C)[1]), "+f"((C)[2]), "+f"((C)[3]) \
    : "r"((A)[0]), "r"((A)[1]), "r"((A)[2]), "r"((A)[3]), \
      "r"((Bf)[0]), "r"((Bf)[1]))

__device__ __forceinline__ void cpa16(void* dst, const void* src, bool pred) {
    uint32_t d = (uint32_t)__cvta_generic_to_shared(dst);
    int sz = pred ? 16 : 0;
    asm volatile("cp.async.cg.shared.global [%0], [%1], 16, %2;"
                 :: "r"(d), "l"(src), "r"(sz) : "memory");
}
__device__ __forceinline__ void cpa_commit() {
    asm volatile("cp.async.commit_group;" ::: "memory");
}
__device__ __forceinline__ void cpa_wait_all() {
    asm volatile("cp.async.wait_group 0;" ::: "memory");
}

// load hs tile (m-block) hi+lo into (Ah, Al); 256 threads, 16 iters each
__device__ __forceinline__ void load_A(char* Ah, char* Al, int m0, int tid) {
    #pragma unroll
    for (int it = 0; it < 8; it++) {
        int id  = it * 256 + tid;
        int row = id >> 4;
        int c   = (id & 15) * 8;
        int so  = row * (LDA2 * 2) + c * 2;
        const size_t g = (size_t)(m0 + row) * H_DIM + c;
        cpa16(Ah + so, &g_hs_hi[g], true);
        cpa16(Al + so, &g_hs_lo[g], true);
    }
}
// load Vw tile (n-block) hi+lo into (Bh, Bl), zero-fill rows >= V_DIM
__device__ __forceinline__ void load_B(char* Bh, char* Bl, int n0, int tid) {
    #pragma unroll
    for (int it = 0; it < 8; it++) {
        int id  = it * 256 + tid;
        int row = id >> 4;
        int c   = (id & 15) * 8;
        int so  = row * (LDA2 * 2) + c * 2;
        bool ok = (n0 + row) < V_DIM;
        const size_t g = (size_t)(n0 + row) * H_DIM + c;
        cpa16(Bh + so, &g_vw_hi[g], ok);
        cpa16(Bl + so, &g_vw_lo[g], ok);
    }
}

__global__ void __launch_bounds__(256) out_gemm_kernel(
    const float* __restrict__ Vb, float* __restrict__ out)
{
    extern __shared__ __align__(16) char dynsm[];
    char* Bh    = dynsm;
    char* Bl    = dynsm + 1 * TILE_B;
    char* AhBuf = dynsm + 2 * TILE_B;          // [2] stream buffers
    char* AlBuf = dynsm + 4 * TILE_B;

    const int tid  = threadIdx.x;
    const int w    = tid >> 5;
    const int lane = tid & 31;
    const int wm = (w >> 2) * 64;   // 0 or 64
    const int wn = (w & 3) * 32;    // 0,32,64,96

    const int c  = blockIdx.x;
    const int lo = (c * NT) / GRID_GEMM;
    const int hi = ((c + 1) * NT) / GRID_GEMM;
    if (lo >= hi) return;

    // prologue: resident B for first tile's n, stream A into buf 0
    load_B(Bh, Bl, (lo / MB) * 128, tid);
    load_A(AhBuf, AlBuf, (lo % MB) * 128, tid);
    cpa_commit();
    cpa_wait_all();
    __syncthreads();

    const int a_rl = lane & 15;
    const int a_co = (lane >> 4) * 8;
    const int b_rl = lane & 7;
    const int b_co = lane & 8;

    int buf = 0;
    for (int t = lo; t < hi; t++) {
        const int m0 = (t % MB) * 128;
        const int n0 = (t / MB) * 128;
        char* Ah = AhBuf + buf * TILE_B;
        char* Al = AlBuf + buf * TILE_B;

        // prefetch next A tile into the other buffer
        if (t + 1 < hi) {
            load_A(AhBuf + (buf ^ 1) * TILE_B, AlBuf + (buf ^ 1) * TILE_B,
                   ((t + 1) % MB) * 128, tid);
        }
        cpa_commit();

        // ---- mma on current buffers ----
        float acc[4][4][4];
        #pragma unroll
        for (int i = 0; i < 4; i++)
            #pragma unroll
            for (int jj = 0; jj < 4; jj++)
                #pragma unroll
                for (int k = 0; k < 4; k++) acc[i][jj][k] = 0.0f;

        #pragma unroll 1
        for (int kc = 0; kc < 8; kc++) {
            const int kb = kc * 16;
            unsigned ah[4][4], al[4][4];
            #pragma unroll
            for (int rb = 0; rb < 4; rb++) {
                unsigned adr = (unsigned)__cvta_generic_to_shared(
                    Ah + (wm + rb * 16 + a_rl) * (LDA2 * 2) + (kb + a_co) * 2);
                asm volatile("ldmatrix.sync.aligned.m8n8.x4.shared.b16 {%0,%1,%2,%3}, [%4];"
                    : "=r"(ah[rb][0]), "=r"(ah[rb][1]), "=r"(ah[rb][2]), "=r"(ah[rb][3])
                    : "r"(adr));
                adr = (unsigned)__cvta_generic_to_shared(
                    Al + (wm + rb * 16 + a_rl) * (LDA2 * 2) + (kb + a_co) * 2);
                asm volatile("ldmatrix.sync.aligned.m8n8.x4.shared.b16 {%0,%1,%2,%3}, [%4];"
                    : "=r"(al[rb][0]), "=r"(al[rb][1]), "=r"(al[rb][2]), "=r"(al[rb][3])
                    : "r"(adr));
            }
            unsigned bh[4][2], bl[4][2];
            #pragma unroll
            for (int cb = 0; cb < 4; cb++) {
                unsigned adr = (unsigned)__cvta_generic_to_shared(
                    Bh + (wn + cb * 8 + b_rl) * (LDA2 * 2) + (kb + b_co) * 2);
                asm volatile("ldmatrix.sync.aligned.m8n8.x2.shared.b16 {%0,%1}, [%2];"
                    : "=r"(bh[cb][0]), "=r"(bh[cb][1]) : "r"(adr));
                adr = (unsigned)__cvta_generic_to_shared(
                    Bl + (wn + cb * 8 + b_rl) * (LDA2 * 2) + (kb + b_co) * 2);
                asm volatile("ldmatrix.sync.aligned.m8n8.x2.shared.b16 {%0,%1}, [%2];"
                    : "=r"(bl[cb][0]), "=r"(bl[cb][1]) : "r"(adr));
            }
            #pragma unroll
            for (int rb = 0; rb < 4; rb++)
                #pragma unroll
                for (int cb = 0; cb < 4; cb++) {
                    MMA_BF16(acc[rb][cb], ah[rb], bh[cb]);
                    MMA_BF16(acc[rb][cb], ah[rb], bl[cb]);
                    MMA_BF16(acc[rb][cb], al[rb], bh[cb]);
                }
        }

        // ---- epilogue ----
        #pragma unroll
        for (int rb = 0; rb < 4; rb++) {
            int row = m0 + wm + rb * 16 + (lane >> 2);
            #pragma unroll
            for (int cb = 0; cb < 4; cb++) {
                int col = n0 + wn + cb * 8 + (lane & 3) * 2;
                if (col < V_DIM) {
                    float2 bv = *(const float2*)&Vb[col];
                    float2 o0, o1;
                    o0.x = acc[rb][cb][0] + bv.x; o0.y = acc[rb][cb][1] + bv.y;
                    o1.x = acc[rb][cb][2] + bv.x; o1.y = acc[rb][cb][3] + bv.y;
                    *(float2*)&out[(size_t)row * V_DIM + col] = o0;
                    *(float2*)&out[(size_t)(row + 8) * V_DIM + col] = o1;
                }
            }
        }

        cpa_wait_all();
        __syncthreads();
        buf ^= 1;

        // n-block change -> reload resident B (rare: <=1-2 per CTA)
        if (t + 1 < hi && (t + 1) / MB != t / MB) {
            load_B(Bh, Bl, ((t + 1) / MB) * 128, tid);
            cpa_commit();
            cpa_wait_all();
            __syncthreads();
        }
    }
}

// ---------------- launch ----------------------------------------------------
extern "C" void kernel_launch(void* const* d_in, const int* in_sizes, int n_in,
                              void* d_out, int out_size) {
    const float* x  = (const float*)d_in[0];
    const float* Ww = (const float*)d_in[1];
    const float* Wb = (const float*)d_in[2];
    const float* Uw = (const float*)d_in[3];
    const float* Ub = (const float*)d_in[4];
    const float* Vw = (const float*)d_in[5];
    const float* Vb = (const float*)d_in[6];
    float* out = (float*)d_out;

    cudaFuncSetAttribute(out_gemm_kernel,
                         cudaFuncAttributeMaxDynamicSharedMemorySize, GEMM_SMEM);

    rec_split_kernel<<<128, 512>>>(x, Ww, Wb, Uw, Ub, Vw, out + OUT_SEQ_ELEMS);
    out_gemm_kernel<<<GRID_GEMM, 256, GEMM_SMEM>>>(Vb, out);
}

// round 4
// speedup vs baseline: 1.2828x; 1.1707x over previous
#include <cuda_runtime.h>
#include <cuda_bf16.h>
#include <cstdint>

#define B_SZ    32
#define T_STEPS 200
#define E_DIM   32
#define H_DIM   128
#define V_DIM   8000
#define M_TOT   (B_SZ * T_STEPS)          // 6400 rows of hs
#define OUT_SEQ_ELEMS ((size_t)M_TOT * V_DIM)

#define MB 50                              // m-tiles (6400/128)
#define NB 63                              // n-tiles (ceil 8000/128)
#define NT (MB * NB)                       // 3150 tiles
#define GRID_GEMM 148

// ---------------- scratch (no allocation allowed -> device globals) ----------
__device__ __align__(128) __nv_bfloat16 g_hs_hi[M_TOT * H_DIM];
__device__ __align__(128) __nv_bfloat16 g_hs_lo[M_TOT * H_DIM];
__device__ __align__(128) __nv_bfloat16 g_vw_hi[V_DIM * H_DIM];
__device__ __align__(128) __nv_bfloat16 g_vw_lo[V_DIM * H_DIM];

// ---------------- kernel 1: fused recurrence (blocks 0..31) + Vw split ------
// 256 threads: tid = j*2 + q. Thread (j,q) owns Ww[j][q*64 .. q*64+63] and
// Uw[j][q*16 .. q*16+15] in registers; 4 independent accumulators keep the
// FFMA chain 16 deep; single shfl reduce; tanh via ex2/rcp approx.
__global__ void __launch_bounds__(256) rec_split_kernel(
    const float* __restrict__ x,  const float* __restrict__ Ww,
    const float* __restrict__ Wb, const float* __restrict__ Uw,
    const float* __restrict__ Ub, const float* __restrict__ Vw,
    float* __restrict__ hidden_out)
{
    __shared__ __align__(16) float xs[T_STEPS * E_DIM];   // 25.6 KB
    __shared__ __align__(16) float hbuf[2][136];          // 2 chunks, stride 68

    const int tid = threadIdx.x;

    if (blockIdx.x >= B_SZ) {
        // ---- Vw split on the other SMs ----
        const int nblk = gridDim.x - B_SZ;
        for (int i = (blockIdx.x - B_SZ) * 256 + tid; i < V_DIM * H_DIM;
             i += nblk * 256) {
            float v = Vw[i];
            __nv_bfloat16 h = __float2bfloat16(v);
            g_vw_hi[i] = h;
            g_vw_lo[i] = __float2bfloat16(v - __bfloat162float(h));
        }
        return;
    }

    const int b = blockIdx.x;
    const int j = tid >> 1;
    const int q = tid & 1;

    const float* xb = x + (size_t)b * T_STEPS * E_DIM;
    for (int i = tid; i < T_STEPS * E_DIM; i += 256) xs[i] = xb[i];
    if (tid < 136) { hbuf[0][tid] = 0.0f; hbuf[1][tid] = 0.0f; }

    // weights -> registers: 64 Ww + 16 Uw floats
    float wreg[64];
    {
        const float4* wr = (const float4*)(Ww + j * H_DIM + q * 64);
        #pragma unroll
        for (int i = 0; i < 16; i++) {
            float4 v = wr[i];
            wreg[4*i+0] = v.x; wreg[4*i+1] = v.y;
            wreg[4*i+2] = v.z; wreg[4*i+3] = v.w;
        }
    }
    float ureg[16];
    {
        const float4* ur = (const float4*)(Uw + j * E_DIM + q * 16);
        #pragma unroll
        for (int i = 0; i < 4; i++) {
            float4 v = ur[i];
            ureg[4*i+0] = v.x; ureg[4*i+1] = v.y;
            ureg[4*i+2] = v.z; ureg[4*i+3] = v.w;
        }
    }
    const float bias = Wb[j] + Ub[j];
    __syncthreads();

    const int hoff = q * 68;                 // chunk q base (stride 68 floats)
    const int wchunk = j >> 6;               // which chunk j's h value lives in
    const int wpos   = (j & 63) + wchunk * 68;

    for (int t = 0; t < T_STEPS; t++) {
        const float4* hr = (const float4*)(&hbuf[t & 1][hoff]);
        float a0 = 0.f, a1 = 0.f, a2 = 0.f, a3 = 0.f;
        #pragma unroll
        for (int g = 0; g < 4; g++) {
            float4 h0 = hr[4*g+0], h1 = hr[4*g+1], h2 = hr[4*g+2], h3 = hr[4*g+3];
            const float* w = wreg + 16 * g;
            a0 += w[0]*h0.x  + w[1]*h0.y  + w[2]*h0.z  + w[3]*h0.w;
            a1 += w[4]*h1.x  + w[5]*h1.y  + w[6]*h1.z  + w[7]*h1.w;
            a2 += w[8]*h2.x  + w[9]*h2.y  + w[10]*h2.z + w[11]*h2.w;
            a3 += w[12]*h3.x + w[13]*h3.y + w[14]*h3.z + w[15]*h3.w;
        }
        {
            const float4* xt = (const float4*)(&xs[t * E_DIM + q * 16]);
            float4 x0 = xt[0], x1 = xt[1], x2 = xt[2], x3 = xt[3];
            a0 += ureg[0]*x0.x  + ureg[1]*x0.y  + ureg[2]*x0.z  + ureg[3]*x0.w;
            a1 += ureg[4]*x1.x  + ureg[5]*x1.y  + ureg[6]*x1.z  + ureg[7]*x1.w;
            a2 += ureg[8]*x2.x  + ureg[9]*x2.y  + ureg[10]*x2.z + ureg[11]*x2.w;
            a3 += ureg[12]*x3.x + ureg[13]*x3.y + ureg[14]*x3.z + ureg[15]*x3.w;
        }
        float acc = (a0 + a1) + (a2 + a3);
        acc += __shfl_xor_sync(0xffffffffu, acc, 1);   // combine the 2 k-halves
        acc += bias;

        // tanh(x) = 1 - 2/(exp(2x)+1) via fast MUFU ops (~1e-6 rel err)
        float xcl = fminf(fmaxf(acc, -15.0f), 15.0f);
        float e;
        asm("ex2.approx.f32 %0, %1;" : "=f"(e) : "f"(xcl * 2.8853900817779268f));
        float r;
        asm("rcp.approx.f32 %0, %1;" : "=f"(r) : "f"(e + 1.0f));
        float hv = fmaf(-2.0f, r, 1.0f);

        if (q == 0) hbuf[(t + 1) & 1][wpos] = hv;
        __nv_bfloat16 hi = __float2bfloat16(hv);
        size_t gi = ((size_t)b * T_STEPS + t) * H_DIM + j;
        if (q == 0) g_hs_hi[gi] = hi;
        else        g_hs_lo[gi] = __float2bfloat16(hv - __bfloat162float(hi));
        if (q == 1 && t == T_STEPS - 1) hidden_out[b * H_DIM + j] = hv;
        __syncthreads();
    }
}

// ---------------- kernel 2: persistent split-bf16 GEMM (mma.sync) -----------
// C[6400,8000] = hs @ Vw^T + Vb. 128x128 tiles, n-major order: B (Vw) tile
// resident, A (hs) streamed double-buffered via cp.async. 512 threads,
// 16 warps as 4(M)x4(N) of 32x32 warp tiles for latency hiding.
#define LDA2 136                               // bf16/row: 272B, conflict-free
#define TILE_B (128 * LDA2 * 2)                // 34816 B per tile
#define GEMM_SMEM (6 * TILE_B + 1024)          // 209920 B

#define MMA_BF16(C, A, Bf) asm volatile( \
    "mma.sync.aligned.m16n8k16.row.col.f32.bf16.bf16.f32 " \
    "{%0,%1,%2,%3}, {%4,%5,%6,%7}, {%8,%9}, {%0,%1,%2,%3};" \
    : "+f"((C)[0]), "+f"((C)[1]), "+f"((C)[2]), "+f"((C)[3]) \
    : "r"((A)[0]), "r"((A)[1]), "r"((A)[2]), "r"((A)[3]), \
      "r"((Bf)[0]), "r"((Bf)[1]))

__device__ __forceinline__ void cpa16(void* dst, const void* src, bool pred) {
    uint32_t d = (uint32_t)__cvta_generic_to_shared(dst);
    int sz = pred ? 16 : 0;
    asm volatile("cp.async.cg.shared.global [%0], [%1], 16, %2;"
                 :: "r"(d), "l"(src), "r"(sz) : "memory");
}
__device__ __forceinline__ void cpa_commit() {
    asm volatile("cp.async.commit_group;" ::: "memory");
}
__device__ __forceinline__ void cpa_wait_all() {
    asm volatile("cp.async.wait_group 0;" ::: "memory");
}

// load hs tile (m-block) hi+lo; 512 threads x 4 iters x 16B per tile
__device__ __forceinline__ void load_A(char* Ah, char* Al, int m0, int tid) {
    #pragma unroll
    for (int it = 0; it < 4; it++) {
        int id  = it * 512 + tid;
        int row = id >> 4;
        int c   = (id & 15) * 8;
        int so  = row * (LDA2 * 2) + c * 2;
        const size_t g = (size_t)(m0 + row) * H_DIM + c;
        cpa16(Ah + so, &g_hs_hi[g], true);
        cpa16(Al + so, &g_hs_lo[g], true);
    }
}
// load Vw tile (n-block), zero-fill rows >= V_DIM
__device__ __forceinline__ void load_B(char* Bh, char* Bl, int n0, int tid) {
    #pragma unroll
    for (int it = 0; it < 4; it++) {
        int id  = it * 512 + tid;
        int row = id >> 4;
        int c   = (id & 15) * 8;
        int so  = row * (LDA2 * 2) + c * 2;
        bool ok = (n0 + row) < V_DIM;
        const size_t g = (size_t)(n0 + row) * H_DIM + c;
        cpa16(Bh + so, &g_vw_hi[g], ok);
        cpa16(Bl + so, &g_vw_lo[g], ok);
    }
}

__global__ void __launch_bounds__(512) out_gemm_kernel(
    const float* __restrict__ Vb, float* __restrict__ out)
{
    extern __shared__ __align__(16) char dynsm[];
    char* Bh    = dynsm;
    char* Bl    = dynsm + 1 * TILE_B;
    char* AhBuf = dynsm + 2 * TILE_B;          // [2] stream buffers
    char* AlBuf = dynsm + 4 * TILE_B;

    const int tid  = threadIdx.x;
    const int w    = tid >> 5;
    const int lane = tid & 31;
    const int wm = (w >> 2) * 32;   // 0,32,64,96
    const int wn = (w & 3) * 32;    // 0,32,64,96

    const int c  = blockIdx.x;
    const int lo = (c * NT) / GRID_GEMM;
    const int hi = ((c + 1) * NT) / GRID_GEMM;
    if (lo >= hi) return;

    load_B(Bh, Bl, (lo / MB) * 128, tid);
    load_A(AhBuf, AlBuf, (lo % MB) * 128, tid);
    cpa_commit();
    cpa_wait_all();
    __syncthreads();

    const int a_rl = lane & 15;
    const int a_co = (lane >> 4) * 8;
    const int b_rl = lane & 7;
    const int b_co = lane & 8;

    int buf = 0;
    for (int t = lo; t < hi; t++) {
        const int m0 = (t % MB) * 128;
        const int n0 = (t / MB) * 128;
        char* Ah = AhBuf + buf * TILE_B;
        char* Al = AlBuf + buf * TILE_B;

        if (t + 1 < hi) {
            load_A(AhBuf + (buf ^ 1) * TILE_B, AlBuf + (buf ^ 1) * TILE_B,
                   ((t + 1) % MB) * 128, tid);
        }
        cpa_commit();

        float acc[2][4][4];
        #pragma unroll
        for (int i = 0; i < 2; i++)
            #pragma unroll
            for (int jj = 0; jj < 4; jj++)
                #pragma unroll
                for (int k = 0; k < 4; k++) acc[i][jj][k] = 0.0f;

        #pragma unroll 1
        for (int kc = 0; kc < 8; kc++) {
            const int kb = kc * 16;
            unsigned ah[2][4], al[2][4];
            #pragma unroll
            for (int rb = 0; rb < 2; rb++) {
                unsigned adr = (unsigned)__cvta_generic_to_shared(
                    Ah + (wm + rb * 16 + a_rl) * (LDA2 * 2) + (kb + a_co) * 2);
                asm volatile("ldmatrix.sync.aligned.m8n8.x4.shared.b16 {%0,%1,%2,%3}, [%4];"
                    : "=r"(ah[rb][0]), "=r"(ah[rb][1]), "=r"(ah[rb][2]), "=r"(ah[rb][3])
                    : "r"(adr));
                adr = (unsigned)__cvta_generic_to_shared(
                    Al + (wm + rb * 16 + a_rl) * (LDA2 * 2) + (kb + a_co) * 2);
                asm volatile("ldmatrix.sync.aligned.m8n8.x4.shared.b16 {%0,%1,%2,%3}, [%4];"
                    : "=r"(al[rb][0]), "=r"(al[rb][1]), "=r"(al[rb][2]), "=r"(al[rb][3])
                    : "r"(adr));
            }
            unsigned bh[4][2], bl[4][2];
            #pragma unroll
            for (int cb = 0; cb < 4; cb++) {
                unsigned adr = (unsigned)__cvta_generic_to_shared(
                    Bh + (wn + cb * 8 + b_rl) * (LDA2 * 2) + (kb + b_co) * 2);
                asm volatile("ldmatrix.sync.aligned.m8n8.x2.shared.b16 {%0,%1}, [%2];"
                    : "=r"(bh[cb][0]), "=r"(bh[cb][1]) : "r"(adr));
                adr = (unsigned)__cvta_generic_to_shared(
                    Bl + (wn + cb * 8 + b_rl) * (LDA2 * 2) + (kb + b_co) * 2);
                asm volatile("ldmatrix.sync.aligned.m8n8.x2.shared.b16 {%0,%1}, [%2];"
                    : "=r"(bl[cb][0]), "=r"(bl[cb][1]) : "r"(adr));
            }
            #pragma unroll
            for (int rb = 0; rb < 2; rb++)
                #pragma unroll
                for (int cb = 0; cb < 4; cb++) {
                    MMA_BF16(acc[rb][cb], ah[rb], bh[cb]);
                    MMA_BF16(acc[rb][cb], ah[rb], bl[cb]);
                    MMA_BF16(acc[rb][cb], al[rb], bh[cb]);
                }
        }

        #pragma unroll
        for (int rb = 0; rb < 2; rb++) {
            int row = m0 + wm + rb * 16 + (lane >> 2);
            #pragma unroll
            for (int cb = 0; cb < 4; cb++) {
                int col = n0 + wn + cb * 8 + (lane & 3) * 2;
                if (col < V_DIM) {
                    float2 bv = *(const float2*)&Vb[col];
                    float2 o0, o1;
                    o0.x = acc[rb][cb][0] + bv.x; o0.y = acc[rb][cb][1] + bv.y;
                    o1.x = acc[rb][cb][2] + bv.x; o1.y = acc[rb][cb][3] + bv.y;
                    *(float2*)&out[(size_t)row * V_DIM + col] = o0;
                    *(float2*)&out[(size_t)(row + 8) * V_DIM + col] = o1;
                }
            }
        }

        cpa_wait_all();
        __syncthreads();
        buf ^= 1;

        if (t + 1 < hi && (t + 1) / MB != t / MB) {
            load_B(Bh, Bl, ((t + 1) / MB) * 128, tid);
            cpa_commit();
            cpa_wait_all();
            __syncthreads();
        }
    }
}

// ---------------- launch ----------------------------------------------------
extern "C" void kernel_launch(void* const* d_in, const int* in_sizes, int n_in,
                              void* d_out, int out_size) {
    const float* x  = (const float*)d_in[0];
    const float* Ww = (const float*)d_in[1];
    const float* Wb = (const float*)d_in[2];
    const float* Uw = (const float*)d_in[3];
    const float* Ub = (const float*)d_in[4];
    const float* Vw = (const float*)d_in[5];
    const float* Vb = (const float*)d_in[6];
    float* out = (float*)d_out;

    cudaFuncSetAttribute(out_gemm_kernel,
                         cudaFuncAttributeMaxDynamicSharedMemorySize, GEMM_SMEM);

    rec_split_kernel<<<128, 256>>>(x, Ww, Wb, Uw, Ub, Vw, out + OUT_SEQ_ELEMS);
    out_gemm_kernel<<<GRID_GEMM, 512, GEMM_SMEM>>>(Vb, out);
}

// round 6
// speedup vs baseline: 1.4186x; 1.1059x over previous
#include <cuda_runtime.h>
#include <cuda_bf16.h>
#include <cstdint>

#define B_SZ    32
#define T_STEPS 200
#define E_DIM   32
#define H_DIM   128
#define V_DIM   8000
#define M_TOT   (B_SZ * T_STEPS)          // 6400 rows of hs
#define OUT_SEQ_ELEMS ((size_t)M_TOT * V_DIM)

#define MB 50
#define NB 63
#define NT (MB * NB)
#define GRID_GEMM 148

// ---------------- scratch ----------------------------------------------------
__device__ __align__(128) __nv_bfloat16 g_hs_hi[M_TOT * H_DIM];
__device__ __align__(128) __nv_bfloat16 g_hs_lo[M_TOT * H_DIM];
__device__ __align__(128) __nv_bfloat16 g_vw_hi[V_DIM * H_DIM];
__device__ __align__(128) __nv_bfloat16 g_vw_lo[V_DIM * H_DIM];

// ---------------- packed f32x2 helpers ---------------------------------------
typedef unsigned long long ull;
__device__ __forceinline__ void fma2(ull& d, ull a, ull b) {
    asm("fma.rn.f32x2 %0, %1, %2, %0;" : "+l"(d) : "l"(a), "l"(b));
}
__device__ __forceinline__ ull pk(float x, float y) {
    ull r; asm("mov.b64 %0, {%1,%2};" : "=l"(r) : "f"(x), "f"(y)); return r;
}
__device__ __forceinline__ float2 upk(ull v) {
    float2 r; asm("mov.b64 {%0,%1}, %2;" : "=f"(r.x), "=f"(r.y) : "l"(v)); return r;
}

// ---------------- kernel 1: recurrence (blocks 0..31) + Vw split ------------
// dyn smem: ux[200*128] fp32 | xs[200*32] | hbuf[2][136] (stride-68 chunks,
// 16B-aligned AND 4-bank offset between the two q chunks)
#define REC_UX   0
#define REC_XS   (T_STEPS * H_DIM)                 // 25600
#define REC_HB   (REC_XS + T_STEPS * E_DIM)        // 32000
#define REC_SMEM ((REC_HB + 2 * 136) * 4)          // 129088 B

__global__ void __launch_bounds__(256) rec_split_kernel(
    const float* __restrict__ x,  const float* __restrict__ Ww,
    const float* __restrict__ Wb, const float* __restrict__ Uw,
    const float* __restrict__ Ub, const float* __restrict__ Vw,
    float* __restrict__ hidden_out)
{
    const int tid = threadIdx.x;

    if (blockIdx.x >= B_SZ) {
        const int nblk = gridDim.x - B_SZ;
        for (int i = (blockIdx.x - B_SZ) * 256 + tid; i < V_DIM * H_DIM;
             i += nblk * 256) {
            float v = Vw[i];
            __nv_bfloat16 h = __float2bfloat16(v);
            g_vw_hi[i] = h;
            g_vw_lo[i] = __float2bfloat16(v - __bfloat162float(h));
        }
        return;
    }

    extern __shared__ __align__(16) float rsm[];
    float* ux = rsm + REC_UX;
    float* xs = rsm + REC_XS;
    float* hb = rsm + REC_HB;

    const int b = blockIdx.x;

    // phase 0: x[b] -> smem
    const float* xb = x + (size_t)b * T_STEPS * E_DIM;
    for (int i = tid; i < T_STEPS * E_DIM; i += 256) xs[i] = xb[i];
    if (tid < 136) { hb[tid] = 0.0f; hb[136 + tid] = 0.0f; }
    __syncthreads();

    // phase 1: bulk input projection ux[t][j] = Uw[j]·x[t] + Wb[j] + Ub[j]
    {
        const int jj = tid & 127;
        const int g  = tid >> 7;                  // t-half
        ull up[16];
        const float2* ur = (const float2*)(Uw + jj * E_DIM);
        #pragma unroll
        for (int i = 0; i < 16; i++) { float2 v = ur[i]; up[i] = pk(v.x, v.y); }
        const float biasj = Wb[jj] + Ub[jj];
        for (int t = g * 100; t < g * 100 + 100; t++) {
            ull a0 = pk(0.f, 0.f), a1 = a0, a2 = a0, a3 = a0;
            const float4* xt = (const float4*)(xs + t * E_DIM);
            #pragma unroll
            for (int i = 0; i < 8; i++) {
                float4 v = xt[i];
                fma2((i & 1) ? a1 : a0, up[2 * i],     pk(v.x, v.y));
                fma2((i & 1) ? a3 : a2, up[2 * i + 1], pk(v.z, v.w));
            }
            float2 s0 = upk(a0), s1 = upk(a1), s2 = upk(a2), s3 = upk(a3);
            ux[t * H_DIM + jj] = ((s0.x + s0.y) + (s1.x + s1.y))
                               + ((s2.x + s2.y) + (s3.x + s3.y)) + biasj;
        }
    }

    // phase 2: recurrence. tid = j*2 + q; thread owns Ww[j][q*64..q*64+63]
    const int j = tid >> 1;
    const int q = tid & 1;
    ull wp[32];
    {
        const float4* wr = (const float4*)(Ww + j * H_DIM + q * 64);
        #pragma unroll
        for (int i = 0; i < 16; i++) {
            float4 v = wr[i];
            wp[2 * i]     = pk(v.x, v.y);
            wp[2 * i + 1] = pk(v.z, v.w);
        }
    }
    __syncthreads();

    const int hrd = q * 68;                       // chunk base (272B: aligned)
    const int wch = (j >> 6) * 68 + (j & 63);     // write pos for h[j]

    for (int t = 0; t < T_STEPS; t++) {
        const float4* hr = (const float4*)(hb + (t & 1) * 136 + hrd);
        ull a0 = pk(0.f, 0.f), a1 = a0, a2 = a0, a3 = a0;
        #pragma unroll
        for (int i = 0; i < 16; i++) {
            float4 v = hr[i];
            ull lo = pk(v.x, v.y), hi = pk(v.z, v.w);
            switch (i & 3) {
                case 0: fma2(a0, wp[2*i], lo); fma2(a1, wp[2*i+1], hi); break;
                case 1: fma2(a2, wp[2*i], lo); fma2(a3, wp[2*i+1], hi); break;
                case 2: fma2(a1, wp[2*i], lo); fma2(a0, wp[2*i+1], hi); break;
                default:fma2(a3, wp[2*i], lo); fma2(a2, wp[2*i+1], hi); break;
            }
        }
        float2 s0 = upk(a0), s1 = upk(a1), s2 = upk(a2), s3 = upk(a3);
        float acc = ((s0.x + s0.y) + (s1.x + s1.y))
                  + ((s2.x + s2.y) + (s3.x + s3.y));
        acc += __shfl_xor_sync(0xffffffffu, acc, 1);
        acc += ux[t * H_DIM + j];

        // tanh(x) = 1 - 2/(exp(2x)+1)
        float xcl = fminf(fmaxf(acc, -15.0f), 15.0f);
        float e;
        asm("ex2.approx.f32 %0, %1;" : "=f"(e) : "f"(xcl * 2.8853900817779268f));
        float r;
        asm("rcp.approx.f32 %0, %1;" : "=f"(r) : "f"(e + 1.0f));
        float hv = fmaf(-2.0f, r, 1.0f);

        if (q == 0) hb[((t + 1) & 1) * 136 + wch] = hv;
        __nv_bfloat16 hi16 = __float2bfloat16(hv);
        size_t gi = ((size_t)b * T_STEPS + t) * H_DIM + j;
        if (q == 0) g_hs_hi[gi] = hi16;
        else        g_hs_lo[gi] = __float2bfloat16(hv - __bfloat162float(hi16));
        if (q == 1 && t == T_STEPS - 1) hidden_out[b * H_DIM + j] = hv;
        __syncthreads();
    }
}

// ---------------- kernel 2: persistent split-bf16 GEMM ----------------------
// 256 threads, 8 warps as 2(M)x4(N) of 64x32 warp tiles; pass-outer MMA order;
// per-kc fragment double buffering; B resident, A cp.async double-buffered.
#define LDA2 136
#define TILE_B (128 * LDA2 * 2)                // 34816
#define GEMM_SMEM (6 * TILE_B + 1024)

#define MMA_BF16(C, A, Bf) asm volatile( \
    "mma.sync.aligned.m16n8k16.row.col.f32.bf16.bf16.f32 " \
    "{%0,%1,%2,%3}, {%4,%5,%6,%7}, {%8,%9}, {%0,%1,%2,%3};" \
    : "+f"((C)[0]), "+f"((C)[1]), "+f"((C)[2]), "+f"((C)[3]) \
    : "r"((A)[0]), "r"((A)[1]), "r"((A)[2]), "r"((A)[3]), \
      "r"((Bf)[0]), "r"((Bf)[1]))

#define LDSM4(R, P) asm volatile( \
    "ldmatrix.sync.aligned.m8n8.x4.shared.b16 {%0,%1,%2,%3}, [%4];" \
    : "=r"((R)[0]), "=r"((R)[1]), "=r"((R)[2]), "=r"((R)[3]) : "r"(P))
#define LDSM2(R, P) asm volatile( \
    "ldmatrix.sync.aligned.m8n8.x2.shared.b16 {%0,%1}, [%2];" \
    : "=r"((R)[0]), "=r"((R)[1]) : "r"(P))

__device__ __forceinline__ void cpa16(void* dst, const void* src, bool pred) {
    uint32_t d = (uint32_t)__cvta_generic_to_shared(dst);
    int sz = pred ? 16 : 0;
    asm volatile("cp.async.cg.shared.global [%0], [%1], 16, %2;"
                 :: "r"(d), "l"(src), "r"(sz) : "memory");
}
__device__ __forceinline__ void cpa_commit() {
    asm volatile("cp.async.commit_group;" ::: "memory");
}
__device__ __forceinline__ void cpa_wait_all() {
    asm volatile("cp.async.wait_group 0;" ::: "memory");
}

__device__ __forceinline__ void load_A(char* Ah, char* Al, int m0, int tid) {
    #pragma unroll
    for (int it = 0; it < 8; it++) {
        int id  = it * 256 + tid;
        int row = id >> 4;
        int c   = (id & 15) * 8;
        int so  = row * (LDA2 * 2) + c * 2;
        const size_t g = (size_t)(m0 + row) * H_DIM + c;
        cpa16(Ah + so, &g_hs_hi[g], true);
        cpa16(Al + so, &g_hs_lo[g], true);
    }
}
__device__ __forceinline__ void load_B(char* Bh, char* Bl, int n0, int tid) {
    #pragma unroll
    for (int it = 0; it < 8; it++) {
        int id  = it * 256 + tid;
        int row = id >> 4;
        int c   = (id & 15) * 8;
        int so  = row * (LDA2 * 2) + c * 2;
        bool ok = (n0 + row) < V_DIM;
        const size_t g = (size_t)(n0 + row) * H_DIM + c;
        cpa16(Bh + so, &g_vw_hi[g], ok);
        cpa16(Bl + so, &g_vw_lo[g], ok);
    }
}

__global__ void __launch_bounds__(256) out_gemm_kernel(
    const float* __restrict__ Vb, float* __restrict__ out)
{
    extern __shared__ __align__(16) char dynsm[];
    char* Bhs   = dynsm;
    char* Bls   = dynsm + 1 * TILE_B;
    char* AhBuf = dynsm + 2 * TILE_B;
    char* AlBuf = dynsm + 4 * TILE_B;

    const int tid  = threadIdx.x;
    const int w    = tid >> 5;
    const int lane = tid & 31;
    const int wm = (w >> 2) * 64;   // 0,64
    const int wn = (w & 3) * 32;    // 0,32,64,96

    const int c  = blockIdx.x;
    const int lo = (c * NT) / GRID_GEMM;
    const int hi = ((c + 1) * NT) / GRID_GEMM;
    if (lo >= hi) return;

    load_B(Bhs, Bls, (lo / MB) * 128, tid);
    load_A(AhBuf, AlBuf, (lo % MB) * 128, tid);
    cpa_commit();
    cpa_wait_all();
    __syncthreads();

    const int a_rl = lane & 15;
    const int a_co = (lane >> 4) * 8;
    const int b_rl = lane & 7;
    const int b_co = lane & 8;

    int buf = 0;
    for (int t = lo; t < hi; t++) {
        const int m0 = (t % MB) * 128;
        const int n0 = (t / MB) * 128;
        char* Ah = AhBuf + buf * TILE_B;
        char* Al = AlBuf + buf * TILE_B;

        if (t + 1 < hi) {
            load_A(AhBuf + (buf ^ 1) * TILE_B, AlBuf + (buf ^ 1) * TILE_B,
                   ((t + 1) % MB) * 128, tid);
        }
        cpa_commit();

        float acc[4][4][4];
        #pragma unroll
        for (int i = 0; i < 4; i++)
            #pragma unroll
            for (int jj = 0; jj < 4; jj++)
                #pragma unroll
                for (int k = 0; k < 4; k++) acc[i][jj][k] = 0.0f;

        // fragment double buffers across kc
        unsigned ah[2][4][4], al[2][4][4], bh[2][4][2], bl[2][4][2];

        // prime kc=0
        #pragma unroll
        for (int rb = 0; rb < 4; rb++) {
            unsigned p = (unsigned)__cvta_generic_to_shared(
                Ah + (wm + rb * 16 + a_rl) * (LDA2 * 2) + a_co * 2);
            LDSM4(ah[0][rb], p);
            p = (unsigned)__cvta_generic_to_shared(
                Al + (wm + rb * 16 + a_rl) * (LDA2 * 2) + a_co * 2);
            LDSM4(al[0][rb], p);
        }
        #pragma unroll
        for (int cb = 0; cb < 4; cb++) {
            unsigned p = (unsigned)__cvta_generic_to_shared(
                Bhs + (wn + cb * 8 + b_rl) * (LDA2 * 2) + b_co * 2);
            LDSM2(bh[0][cb], p);
            p = (unsigned)__cvta_generic_to_shared(
                Bls + (wn + cb * 8 + b_rl) * (LDA2 * 2) + b_co * 2);
            LDSM2(bl[0][cb], p);
        }

        #pragma unroll
        for (int kc = 0; kc < 8; kc++) {
            const int cur = kc & 1, nxt = cur ^ 1;
            if (kc < 7) {
                const int kb = (kc + 1) * 16;
                #pragma unroll
                for (int rb = 0; rb < 4; rb++) {
                    unsigned p = (unsigned)__cvta_generic_to_shared(
                        Ah + (wm + rb * 16 + a_rl) * (LDA2 * 2) + (kb + a_co) * 2);
                    LDSM4(ah[nxt][rb], p);
                    p = (unsigned)__cvta_generic_to_shared(
                        Al + (wm + rb * 16 + a_rl) * (LDA2 * 2) + (kb + a_co) * 2);
                    LDSM4(al[nxt][rb], p);
                }
                #pragma unroll
                for (int cb = 0; cb < 4; cb++) {
                    unsigned p = (unsigned)__cvta_generic_to_shared(
                        Bhs + (wn + cb * 8 + b_rl) * (LDA2 * 2) + (kb + b_co) * 2);
                    LDSM2(bh[nxt][cb], p);
                    p = (unsigned)__cvta_generic_to_shared(
                        Bls + (wn + cb * 8 + b_rl) * (LDA2 * 2) + (kb + b_co) * 2);
                    LDSM2(bl[nxt][cb], p);
                }
            }
            // pass-outer: 16 independent accs between same-acc reuses
            #pragma unroll
            for (int rb = 0; rb < 4; rb++)
                #pragma unroll
                for (int cb = 0; cb < 4; cb++)
                    MMA_BF16(acc[rb][cb], ah[cur][rb], bh[cur][cb]);
            #pragma unroll
            for (int rb = 0; rb < 4; rb++)
                #pragma unroll
                for (int cb = 0; cb < 4; cb++)
                    MMA_BF16(acc[rb][cb], ah[cur][rb], bl[cur][cb]);
            #pragma unroll
            for (int rb = 0; rb < 4; rb++)
                #pragma unroll
                for (int cb = 0; cb < 4; cb++)
                    MMA_BF16(acc[rb][cb], al[cur][rb], bh[cur][cb]);
        }

        #pragma unroll
        for (int rb = 0; rb < 4; rb++) {
            int row = m0 + wm + rb * 16 + (lane >> 2);
            #pragma unroll
            for (int cb = 0; cb < 4; cb++) {
                int col = n0 + wn + cb * 8 + (lane & 3) * 2;
                if (col < V_DIM) {
                    float2 bv = *(const float2*)&Vb[col];
                    float2 o0, o1;
                    o0.x = acc[rb][cb][0] + bv.x; o0.y = acc[rb][cb][1] + bv.y;
                    o1.x = acc[rb][cb][2] + bv.x; o1.y = acc[rb][cb][3] + bv.y;
                    *(float2*)&out[(size_t)row * V_DIM + col] = o0;
                    *(float2*)&out[(size_t)(row + 8) * V_DIM + col] = o1;
                }
            }
        }

        cpa_wait_all();
        __syncthreads();
        buf ^= 1;

        if (t + 1 < hi && (t + 1) / MB != t / MB) {
            load_B(Bhs, Bls, ((t + 1) / MB) * 128, tid);
            cpa_commit();
            cpa_wait_all();
            __syncthreads();
        }
    }
}

// ---------------- launch ----------------------------------------------------
extern "C" void kernel_launch(void* const* d_in, const int* in_sizes, int n_in,
                              void* d_out, int out_size) {
    const float* x  = (const float*)d_in[0];
    const float* Ww = (const float*)d_in[1];
    const float* Wb = (const float*)d_in[2];
    const float* Uw = (const float*)d_in[3];
    const float* Ub = (const float*)d_in[4];
    const float* Vw = (const float*)d_in[5];
    const float* Vb = (const float*)d_in[6];
    float* out = (float*)d_out;

    cudaFuncSetAttribute(rec_split_kernel,
                         cudaFuncAttributeMaxDynamicSharedMemorySize, REC_SMEM);
    cudaFuncSetAttribute(out_gemm_kernel,
                         cudaFuncAttributeMaxDynamicSharedMemorySize, GEMM_SMEM);

    rec_split_kernel<<<128, 256, REC_SMEM>>>(x, Ww, Wb, Uw, Ub, Vw,
                                             out + OUT_SEQ_ELEMS);
    out_gemm_kernel<<<GRID_GEMM, 256, GEMM_SMEM>>>(Vb, out);
}

// round 7
// speedup vs baseline: 1.7782x; 1.2534x over previous
#include <cuda_runtime.h>
#include <cuda_bf16.h>
#include <cuda_fp16.h>
#include <cstdint>

#define B_SZ    32
#define T_STEPS 200
#define E_DIM   32
#define H_DIM   128
#define V_DIM   8000
#define M_TOT   (B_SZ * T_STEPS)
#define OUT_SEQ_ELEMS ((size_t)M_TOT * V_DIM)

#define MB 50
#define NB 63
#define NT (MB * NB)
#define GRID_GEMM 296        // 2 CTAs per SM

// ---------------- scratch ----------------------------------------------------
__device__ __align__(128) __half g_hs_h[M_TOT * H_DIM];
__device__ __align__(128) __half g_vw_h[V_DIM * H_DIM];
__device__ __align__(128) __half g_vw_l[V_DIM * H_DIM];

// ---------------- packed f32x2 helpers ---------------------------------------
typedef unsigned long long ull;
__device__ __forceinline__ void fma2(ull& d, ull a, ull b) {
    asm("fma.rn.f32x2 %0, %1, %2, %0;" : "+l"(d) : "l"(a), "l"(b));
}
__device__ __forceinline__ ull pk(float x, float y) {
    ull r; asm("mov.b64 %0, {%1,%2};" : "=l"(r) : "f"(x), "f"(y)); return r;
}
__device__ __forceinline__ float2 upk(ull v) {
    float2 r; asm("mov.b64 {%0,%1}, %2;" : "=f"(r.x), "=f"(r.y) : "l"(v)); return r;
}

// ---------------- kernel 1: recurrence (blocks 0..31) + Vw fp16 split -------
#define REC_UX   0
#define REC_XS   (T_STEPS * H_DIM)                 // 25600
#define REC_HB   (REC_XS + T_STEPS * E_DIM)        // 32000
#define REC_SMEM ((REC_HB + 2 * 136) * 4)          // 129088 B

__global__ void __launch_bounds__(256) rec_split_kernel(
    const float* __restrict__ x,  const float* __restrict__ Ww,
    const float* __restrict__ Wb, const float* __restrict__ Uw,
    const float* __restrict__ Ub, const float* __restrict__ Vw,
    float* __restrict__ hidden_out)
{
    const int tid = threadIdx.x;

    if (blockIdx.x >= B_SZ) {
        const int nblk = gridDim.x - B_SZ;
        for (int i = (blockIdx.x - B_SZ) * 256 + tid; i < V_DIM * H_DIM;
             i += nblk * 256) {
            float v = Vw[i];
            __half h = __float2half(v);
            g_vw_h[i] = h;
            g_vw_l[i] = __float2half(v - __half2float(h));
        }
        return;
    }

    extern __shared__ __align__(16) float rsm[];
    float* ux = rsm + REC_UX;
    float* xs = rsm + REC_XS;
    float* hb = rsm + REC_HB;

    const int b = blockIdx.x;

    const float* xb = x + (size_t)b * T_STEPS * E_DIM;
    for (int i = tid; i < T_STEPS * E_DIM; i += 256) xs[i] = xb[i];
    if (tid < 136) { hb[tid] = 0.0f; hb[136 + tid] = 0.0f; }
    __syncthreads();

    // phase 1: ux[t][j] = Uw[j]·x[t] + Wb[j] + Ub[j]
    {
        const int jj = tid & 127;
        const int g  = tid >> 7;
        ull up[16];
        const float2* ur = (const float2*)(Uw + jj * E_DIM);
        #pragma unroll
        for (int i = 0; i < 16; i++) { float2 v = ur[i]; up[i] = pk(v.x, v.y); }
        const float biasj = Wb[jj] + Ub[jj];
        for (int t = g * 100; t < g * 100 + 100; t++) {
            ull a0 = pk(0.f, 0.f), a1 = a0, a2 = a0, a3 = a0;
            const float4* xt = (const float4*)(xs + t * E_DIM);
            #pragma unroll
            for (int i = 0; i < 8; i++) {
                float4 v = xt[i];
                fma2((i & 1) ? a1 : a0, up[2 * i],     pk(v.x, v.y));
                fma2((i & 1) ? a3 : a2, up[2 * i + 1], pk(v.z, v.w));
            }
            float2 s0 = upk(a0), s1 = upk(a1), s2 = upk(a2), s3 = upk(a3);
            ux[t * H_DIM + jj] = ((s0.x + s0.y) + (s1.x + s1.y))
                               + ((s2.x + s2.y) + (s3.x + s3.y)) + biasj;
        }
    }

    // phase 2: recurrence
    const int j = tid >> 1;
    const int q = tid & 1;
    ull wp[32];
    {
        const float4* wr = (const float4*)(Ww + j * H_DIM + q * 64);
        #pragma unroll
        for (int i = 0; i < 16; i++) {
            float4 v = wr[i];
            wp[2 * i]     = pk(v.x, v.y);
            wp[2 * i + 1] = pk(v.z, v.w);
        }
    }
    __syncthreads();

    const int hrd = q * 68;
    const int wch = (j >> 6) * 68 + (j & 63);

    for (int t = 0; t < T_STEPS; t++) {
        const float4* hr = (const float4*)(hb + (t & 1) * 136 + hrd);
        ull a0 = pk(0.f, 0.f), a1 = a0, a2 = a0, a3 = a0;
        #pragma unroll
        for (int i = 0; i < 16; i++) {
            float4 v = hr[i];
            ull lo = pk(v.x, v.y), hi = pk(v.z, v.w);
            switch (i & 3) {
                case 0: fma2(a0, wp[2*i], lo); fma2(a1, wp[2*i+1], hi); break;
                case 1: fma2(a2, wp[2*i], lo); fma2(a3, wp[2*i+1], hi); break;
                case 2: fma2(a1, wp[2*i], lo); fma2(a0, wp[2*i+1], hi); break;
                default:fma2(a3, wp[2*i], lo); fma2(a2, wp[2*i+1], hi); break;
            }
        }
        float2 s0 = upk(a0), s1 = upk(a1), s2 = upk(a2), s3 = upk(a3);
        float acc = ((s0.x + s0.y) + (s1.x + s1.y))
                  + ((s2.x + s2.y) + (s3.x + s3.y));
        acc += __shfl_xor_sync(0xffffffffu, acc, 1);
        acc += ux[t * H_DIM + j];

        // tanh(x) = 1 - 2/(exp(2x)+1); inf-safe without clamp
        float e;
        asm("ex2.approx.f32 %0, %1;" : "=f"(e) : "f"(acc * 2.8853900817779268f));
        float r;
        asm("rcp.approx.f32 %0, %1;" : "=f"(r) : "f"(e + 1.0f));
        float hv = fmaf(-2.0f, r, 1.0f);

        if (q == 0) {
            hb[((t + 1) & 1) * 136 + wch] = hv;
            g_hs_h[((size_t)b * T_STEPS + t) * H_DIM + j] = __float2half(hv);
        }
        if (q == 1 && t == T_STEPS - 1) hidden_out[b * H_DIM + j] = hv;
        __syncthreads();
    }
}

// ---------------- kernel 2: persistent fp16 2-pass GEMM ---------------------
// C = Ah·Bh + Ah·Bl  (A = fp16(hs); B = Vw split hi+lo fp16). 128x128 tiles,
// n-major, B resident, A streamed. 2 CTAs/SM: peer CTA hides load/epilogue.
#define LDA2 136
#define TILE_B (128 * LDA2 * 2)                // 34816
#define GEMM_SMEM (3 * TILE_B + 256)           // 104704 B

#define MMA_FP16(C, A, Bf) asm volatile( \
    "mma.sync.aligned.m16n8k16.row.col.f32.f16.f16.f32 " \
    "{%0,%1,%2,%3}, {%4,%5,%6,%7}, {%8,%9}, {%0,%1,%2,%3};" \
    : "+f"((C)[0]), "+f"((C)[1]), "+f"((C)[2]), "+f"((C)[3]) \
    : "r"((A)[0]), "r"((A)[1]), "r"((A)[2]), "r"((A)[3]), \
      "r"((Bf)[0]), "r"((Bf)[1]))

#define LDSM4(R, P) asm volatile( \
    "ldmatrix.sync.aligned.m8n8.x4.shared.b16 {%0,%1,%2,%3}, [%4];" \
    : "=r"((R)[0]), "=r"((R)[1]), "=r"((R)[2]), "=r"((R)[3]) : "r"(P))
#define LDSM2(R, P) asm volatile( \
    "ldmatrix.sync.aligned.m8n8.x2.shared.b16 {%0,%1}, [%2];" \
    : "=r"((R)[0]), "=r"((R)[1]) : "r"(P))

__device__ __forceinline__ void cpa16(void* dst, const void* src, bool pred) {
    uint32_t d = (uint32_t)__cvta_generic_to_shared(dst);
    int sz = pred ? 16 : 0;
    asm volatile("cp.async.cg.shared.global [%0], [%1], 16, %2;"
                 :: "r"(d), "l"(src), "r"(sz) : "memory");
}
__device__ __forceinline__ void cpa_commit() {
    asm volatile("cp.async.commit_group;" ::: "memory");
}
__device__ __forceinline__ void cpa_wait_all() {
    asm volatile("cp.async.wait_group 0;" ::: "memory");
}

__device__ __forceinline__ void load_A(char* Ah, int m0, int tid) {
    #pragma unroll
    for (int it = 0; it < 8; it++) {
        int id  = it * 256 + tid;
        int row = id >> 4;
        int c   = (id & 15) * 8;
        cpa16(Ah + row * (LDA2 * 2) + c * 2,
              &g_hs_h[(size_t)(m0 + row) * H_DIM + c], true);
    }
}
__device__ __forceinline__ void load_B(char* Bh, char* Bl, int n0, int tid) {
    #pragma unroll
    for (int it = 0; it < 8; it++) {
        int id  = it * 256 + tid;
        int row = id >> 4;
        int c   = (id & 15) * 8;
        int so  = row * (LDA2 * 2) + c * 2;
        bool ok = (n0 + row) < V_DIM;
        const size_t g = (size_t)(n0 + row) * H_DIM + c;
        cpa16(Bh + so, &g_vw_h[g], ok);
        cpa16(Bl + so, &g_vw_l[g], ok);
    }
}

__global__ void __launch_bounds__(256, 2) out_gemm_kernel(
    const float* __restrict__ Vb, float* __restrict__ out)
{
    extern __shared__ __align__(16) char dynsm[];
    char* Bhs = dynsm;
    char* Bls = dynsm + 1 * TILE_B;
    char* Ahs = dynsm + 2 * TILE_B;

    const int tid  = threadIdx.x;
    const int w    = tid >> 5;
    const int lane = tid & 31;
    const int wm = (w >> 2) * 64;   // 0,64
    const int wn = (w & 3) * 32;    // 0,32,64,96

    const int c  = blockIdx.x;
    const int lo = (c * NT) / GRID_GEMM;
    const int hi = ((c + 1) * NT) / GRID_GEMM;
    if (lo >= hi) return;

    const int a_rl = lane & 15;
    const int a_co = (lane >> 4) * 8;
    const int b_rl = lane & 7;
    const int b_co = lane & 8;

    int nblk_cur = -1;
    for (int t = lo; t < hi; t++) {
        const int m0 = (t % MB) * 128;
        const int nblk = t / MB;
        const int n0 = nblk * 128;

        // (previous iteration ended with __syncthreads: safe to overwrite smem)
        if (nblk != nblk_cur) { load_B(Bhs, Bls, n0, tid); nblk_cur = nblk; }
        load_A(Ahs, m0, tid);
        cpa_commit();
        cpa_wait_all();
        __syncthreads();

        float acc[4][4][4];
        #pragma unroll
        for (int i = 0; i < 4; i++)
            #pragma unroll
            for (int jj = 0; jj < 4; jj++)
                #pragma unroll
                for (int k = 0; k < 4; k++) acc[i][jj][k] = 0.0f;

        #pragma unroll
        for (int kc = 0; kc < 8; kc++) {
            const int kb = kc * 16;
            unsigned ah[4][4], bh[4][2], bl[4][2];
            #pragma unroll
            for (int rb = 0; rb < 4; rb++) {
                unsigned p = (unsigned)__cvta_generic_to_shared(
                    Ahs + (wm + rb * 16 + a_rl) * (LDA2 * 2) + (kb + a_co) * 2);
                LDSM4(ah[rb], p);
            }
            #pragma unroll
            for (int cb = 0; cb < 4; cb++) {
                unsigned p = (unsigned)__cvta_generic_to_shared(
                    Bhs + (wn + cb * 8 + b_rl) * (LDA2 * 2) + (kb + b_co) * 2);
                LDSM2(bh[cb], p);
                p = (unsigned)__cvta_generic_to_shared(
                    Bls + (wn + cb * 8 + b_rl) * (LDA2 * 2) + (kb + b_co) * 2);
                LDSM2(bl[cb], p);
            }
            #pragma unroll
            for (int rb = 0; rb < 4; rb++)
                #pragma unroll
                for (int cb = 0; cb < 4; cb++)
                    MMA_FP16(acc[rb][cb], ah[rb], bh[cb]);
            #pragma unroll
            for (int rb = 0; rb < 4; rb++)
                #pragma unroll
                for (int cb = 0; cb < 4; cb++)
                    MMA_FP16(acc[rb][cb], ah[rb], bl[cb]);
        }

        #pragma unroll
        for (int rb = 0; rb < 4; rb++) {
            int row = m0 + wm + rb * 16 + (lane >> 2);
            #pragma unroll
            for (int cb = 0; cb < 4; cb++) {
                int col = n0 + wn + cb * 8 + (lane & 3) * 2;
                if (col < V_DIM) {
                    float2 bv = *(const float2*)&Vb[col];
                    float2 o0, o1;
                    o0.x = acc[rb][cb][0] + bv.x; o0.y = acc[rb][cb][1] + bv.y;
                    o1.x = acc[rb][cb][2] + bv.x; o1.y = acc[rb][cb][3] + bv.y;
                    *(float2*)&out[(size_t)row * V_DIM + col] = o0;
                    *(float2*)&out[(size_t)(row + 8) * V_DIM + col] = o1;
                }
            }
        }
        __syncthreads();   // all frag reads done before next tile's cp.async
    }
}

// ---------------- launch ----------------------------------------------------
extern "C" void kernel_launch(void* const* d_in, const int* in_sizes, int n_in,
                              void* d_out, int out_size) {
    const float* x  = (const float*)d_in[0];
    const float* Ww = (const float*)d_in[1];
    const float* Wb = (const float*)d_in[2];
    const float* Uw = (const float*)d_in[3];
    const float* Ub = (const float*)d_in[4];
    const float* Vw = (const float*)d_in[5];
    const float* Vb = (const float*)d_in[6];
    float* out = (float*)d_out;

    cudaFuncSetAttribute(rec_split_kernel,
                         cudaFuncAttributeMaxDynamicSharedMemorySize, REC_SMEM);
    cudaFuncSetAttribute(out_gemm_kernel,
                         cudaFuncAttributeMaxDynamicSharedMemorySize, GEMM_SMEM);

    rec_split_kernel<<<128, 256, REC_SMEM>>>(x, Ww, Wb, Uw, Ub, Vw,
                                             out + OUT_SEQ_ELEMS);
    out_gemm_kernel<<<GRID_GEMM, 256, GEMM_SMEM>>>(Vb, out);
}

// round 8
// speedup vs baseline: 1.7888x; 1.0060x over previous
#include <cuda_runtime.h>
#include <cuda_bf16.h>
#include <cuda_fp16.h>
#include <cstdint>

#define B_SZ    32
#define T_STEPS 200
#define E_DIM   32
#define H_DIM   128
#define V_DIM   8000
#define M_TOT   (B_SZ * T_STEPS)
#define OUT_SEQ_ELEMS ((size_t)M_TOT * V_DIM)

#define MB2 100                 // m-tiles of 64 rows
#define NB  63
#define NT2 (MB2 * NB)          // 6300
#define GRID_GEMM 296           // 2 CTAs/SM

// ---------------- scratch ----------------------------------------------------
__device__ __align__(128) __half g_hs_h[M_TOT * H_DIM];
__device__ __align__(128) __half g_vw_h[V_DIM * H_DIM];
__device__ __align__(128) __half g_vw_l[V_DIM * H_DIM];

// ---------------- packed f32x2 helpers ---------------------------------------
typedef unsigned long long ull;
__device__ __forceinline__ void fma2(ull& d, ull a, ull b) {
    asm("fma.rn.f32x2 %0, %1, %2, %0;" : "+l"(d) : "l"(a), "l"(b));
}
__device__ __forceinline__ ull pk(float x, float y) {
    ull r; asm("mov.b64 %0, {%1,%2};" : "=l"(r) : "f"(x), "f"(y)); return r;
}
__device__ __forceinline__ float2 upk(ull v) {
    float2 r; asm("mov.b64 {%0,%1}, %2;" : "=f"(r.x), "=f"(r.y) : "l"(v)); return r;
}

// ---------------- kernel 1: recurrence (blocks 0..31) + Vw fp16 split -------
#define REC_UX   0
#define REC_XS   (T_STEPS * H_DIM)                 // 25600
#define REC_HB   (REC_XS + T_STEPS * E_DIM)        // 32000
#define REC_SMEM ((REC_HB + 2 * 136) * 4)          // 129088 B

__global__ void __launch_bounds__(256) rec_split_kernel(
    const float* __restrict__ x,  const float* __restrict__ Ww,
    const float* __restrict__ Wb, const float* __restrict__ Uw,
    const float* __restrict__ Ub, const float* __restrict__ Vw,
    float* __restrict__ hidden_out)
{
    const int tid = threadIdx.x;

    if (blockIdx.x >= B_SZ) {
        const int nblk = gridDim.x - B_SZ;
        for (int i = (blockIdx.x - B_SZ) * 256 + tid; i < V_DIM * H_DIM;
             i += nblk * 256) {
            float v = Vw[i];
            __half h = __float2half(v);
            g_vw_h[i] = h;
            g_vw_l[i] = __float2half(v - __half2float(h));
        }
        return;
    }

    extern __shared__ __align__(16) float rsm[];
    float* ux = rsm + REC_UX;
    float* xs = rsm + REC_XS;
    float* hb = rsm + REC_HB;

    const int b = blockIdx.x;

    const float* xb = x + (size_t)b * T_STEPS * E_DIM;
    for (int i = tid; i < T_STEPS * E_DIM; i += 256) xs[i] = xb[i];
    if (tid < 136) { hb[tid] = 0.0f; hb[136 + tid] = 0.0f; }
    __syncthreads();

    // phase 1: ux[t][j] = Uw[j]·x[t] + Wb[j] + Ub[j]
    {
        const int jj = tid & 127;
        const int g  = tid >> 7;
        ull up[16];
        const float2* ur = (const float2*)(Uw + jj * E_DIM);
        #pragma unroll
        for (int i = 0; i < 16; i++) { float2 v = ur[i]; up[i] = pk(v.x, v.y); }
        const float biasj = Wb[jj] + Ub[jj];
        for (int t = g * 100; t < g * 100 + 100; t++) {
            ull a[4];
            a[0] = pk(0.f, 0.f); a[1] = a[0]; a[2] = a[0]; a[3] = a[0];
            const ulonglong2* xt = (const ulonglong2*)(xs + t * E_DIM);
            #pragma unroll
            for (int i = 0; i < 8; i++) {
                ulonglong2 v = xt[i];
                fma2(a[(2 * i) & 3],     up[2 * i],     v.x);
                fma2(a[(2 * i + 1) & 3], up[2 * i + 1], v.y);
            }
            float2 s0 = upk(a[0]), s1 = upk(a[1]), s2 = upk(a[2]), s3 = upk(a[3]);
            ux[t * H_DIM + jj] = ((s0.x + s0.y) + (s1.x + s1.y))
                               + ((s2.x + s2.y) + (s3.x + s3.y)) + biasj;
        }
    }

    // phase 2: recurrence. tid = j*2 + q
    const int j = tid >> 1;
    const int q = tid & 1;
    ull wp[32];
    {
        const float4* wr = (const float4*)(Ww + j * H_DIM + q * 64);
        #pragma unroll
        for (int i = 0; i < 16; i++) {
            float4 v = wr[i];
            wp[2 * i]     = pk(v.x, v.y);
            wp[2 * i + 1] = pk(v.z, v.w);
        }
    }
    __syncthreads();

    const int hrd = q * 68;
    const int wch = (j >> 6) * 68 + (j & 63);

    for (int t = 0; t < T_STEPS; t++) {
        const ulonglong2* hr = (const ulonglong2*)(hb + (t & 1) * 136 + hrd);
        ull a[4];
        a[0] = pk(0.f, 0.f); a[1] = a[0]; a[2] = a[0]; a[3] = a[0];
        #pragma unroll
        for (int i = 0; i < 16; i++) {
            ulonglong2 v = hr[i];                 // LDS.128: two packed pairs
            fma2(a[(2 * i) & 3],     wp[2 * i],     v.x);
            fma2(a[(2 * i + 1) & 3], wp[2 * i + 1], v.y);
        }
        float2 s0 = upk(a[0]), s1 = upk(a[1]), s2 = upk(a[2]), s3 = upk(a[3]);
        float acc = ((s0.x + s0.y) + (s1.x + s1.y))
                  + ((s2.x + s2.y) + (s3.x + s3.y));
        acc += __shfl_xor_sync(0xffffffffu, acc, 1);
        acc += ux[t * H_DIM + j];

        // tanh(x) = 1 - 2/(exp(2x)+1)
        float e;
        asm("ex2.approx.f32 %0, %1;" : "=f"(e) : "f"(acc * 2.8853900817779268f));
        float r;
        asm("rcp.approx.f32 %0, %1;" : "=f"(r) : "f"(e + 1.0f));
        float hv = fmaf(-2.0f, r, 1.0f);

        if (q == 0) {
            hb[((t + 1) & 1) * 136 + wch] = hv;
            g_hs_h[((size_t)b * T_STEPS + t) * H_DIM + j] = __float2half(hv);
        }
        if (q == 1 && t == T_STEPS - 1) hidden_out[b * H_DIM + j] = hv;
        __syncthreads();
    }
}

// ---------------- kernel 2: persistent fp16 2-pass GEMM ---------------------
// C = Ah·(Bh+Bl). CTA tile 64(M)x128(N), K=128. B resident (128 rows hi+lo),
// A double-buffered: prefetch A(t+1) via cp.async during tile-t compute.
// 2 CTAs/SM on top for additional phase overlap.
#define LDA2 136
#define TILE_BN (128 * LDA2 * 2)               // 34816 (B tile)
#define TILE_AM (64 * LDA2 * 2)                // 17408 (A tile)
#define GEMM_SMEM (2 * TILE_BN + 2 * TILE_AM)  // 104448

#define MMA_FP16(C, A, Bf) asm volatile( \
    "mma.sync.aligned.m16n8k16.row.col.f32.f16.f16.f32 " \
    "{%0,%1,%2,%3}, {%4,%5,%6,%7}, {%8,%9}, {%0,%1,%2,%3};" \
    : "+f"((C)[0]), "+f"((C)[1]), "+f"((C)[2]), "+f"((C)[3]) \
    : "r"((A)[0]), "r"((A)[1]), "r"((A)[2]), "r"((A)[3]), \
      "r"((Bf)[0]), "r"((Bf)[1]))

#define LDSM4(R, P) asm volatile( \
    "ldmatrix.sync.aligned.m8n8.x4.shared.b16 {%0,%1,%2,%3}, [%4];" \
    : "=r"((R)[0]), "=r"((R)[1]), "=r"((R)[2]), "=r"((R)[3]) : "r"(P))
#define LDSM2(R, P) asm volatile( \
    "ldmatrix.sync.aligned.m8n8.x2.shared.b16 {%0,%1}, [%2];" \
    : "=r"((R)[0]), "=r"((R)[1]) : "r"(P))

__device__ __forceinline__ void cpa16(void* dst, const void* src, bool pred) {
    uint32_t d = (uint32_t)__cvta_generic_to_shared(dst);
    int sz = pred ? 16 : 0;
    asm volatile("cp.async.cg.shared.global [%0], [%1], 16, %2;"
                 :: "r"(d), "l"(src), "r"(sz) : "memory");
}
__device__ __forceinline__ void cpa_commit() {
    asm volatile("cp.async.commit_group;" ::: "memory");
}
__device__ __forceinline__ void cpa_wait_all() {
    asm volatile("cp.async.wait_group 0;" ::: "memory");
}

// A tile: 64 rows x 128 halfs = 1024 x 16B; 256 threads x 4
__device__ __forceinline__ void load_A(char* Ah, int m0, int tid) {
    #pragma unroll
    for (int it = 0; it < 4; it++) {
        int id  = it * 256 + tid;
        int row = id >> 4;
        int c   = (id & 15) * 8;
        cpa16(Ah + row * (LDA2 * 2) + c * 2,
              &g_hs_h[(size_t)(m0 + row) * H_DIM + c], true);
    }
}
// B tile: 128 rows hi+lo
__device__ __forceinline__ void load_B(char* Bh, char* Bl, int n0, int tid) {
    #pragma unroll
    for (int it = 0; it < 8; it++) {
        int id  = it * 256 + tid;
        int row = id >> 4;
        int c   = (id & 15) * 8;
        int so  = row * (LDA2 * 2) + c * 2;
        bool ok = (n0 + row) < V_DIM;
        const size_t g = (size_t)(n0 + row) * H_DIM + c;
        cpa16(Bh + so, &g_vw_h[g], ok);
        cpa16(Bl + so, &g_vw_l[g], ok);
    }
}

__global__ void __launch_bounds__(256, 2) out_gemm_kernel(
    const float* __restrict__ Vb, float* __restrict__ out)
{
    extern __shared__ __align__(16) char dynsm[];
    char* Bhs = dynsm;
    char* Bls = dynsm + TILE_BN;
    char* Ab0 = dynsm + 2 * TILE_BN;
    char* Ab1 = Ab0 + TILE_AM;

    const int tid  = threadIdx.x;
    const int w    = tid >> 5;
    const int lane = tid & 31;
    const int wm = (w >> 2) * 32;   // 0,32
    const int wn = (w & 3) * 32;    // 0,32,64,96

    const int c  = blockIdx.x;
    const int lo = (c * NT2) / GRID_GEMM;
    const int hi = ((c + 1) * NT2) / GRID_GEMM;
    if (lo >= hi) return;

    const int a_rl = lane & 15;
    const int a_co = (lane >> 4) * 8;
    const int b_rl = lane & 7;
    const int b_co = lane & 8;

    int nblk_cur = lo / MB2;
    load_B(Bhs, Bls, nblk_cur * 128, tid);
    load_A(Ab0, (lo % MB2) * 64, tid);
    cpa_commit();
    cpa_wait_all();
    __syncthreads();

    int buf = 0;
    for (int t = lo; t < hi; t++) {
        const int m0 = (t % MB2) * 64;
        const int nblk = t / MB2;
        const int n0 = nblk * 128;

        if (nblk != nblk_cur) {               // rare (<=1-2 per CTA)
            load_B(Bhs, Bls, n0, tid);
            cpa_commit();
            cpa_wait_all();
            __syncthreads();
            nblk_cur = nblk;
        }

        // prefetch next A tile (overlaps with compute below)
        if (t + 1 < hi) {
            load_A(buf ? Ab0 : Ab1, ((t + 1) % MB2) * 64, tid);
            cpa_commit();
        }

        char* Ahs = buf ? Ab1 : Ab0;

        float acc[2][4][4];
        #pragma unroll
        for (int i = 0; i < 2; i++)
            #pragma unroll
            for (int jj = 0; jj < 4; jj++)
                #pragma unroll
                for (int k = 0; k < 4; k++) acc[i][jj][k] = 0.0f;

        #pragma unroll
        for (int kc = 0; kc < 8; kc++) {
            const int kb = kc * 16;
            unsigned ah[2][4], bh[4][2], bl[4][2];
            #pragma unroll
            for (int rb = 0; rb < 2; rb++) {
                unsigned p = (unsigned)__cvta_generic_to_shared(
                    Ahs + (wm + rb * 16 + a_rl) * (LDA2 * 2) + (kb + a_co) * 2);
                LDSM4(ah[rb], p);
            }
            #pragma unroll
            for (int cb = 0; cb < 4; cb++) {
                unsigned p = (unsigned)__cvta_generic_to_shared(
                    Bhs + (wn + cb * 8 + b_rl) * (LDA2 * 2) + (kb + b_co) * 2);
                LDSM2(bh[cb], p);
                p = (unsigned)__cvta_generic_to_shared(
                    Bls + (wn + cb * 8 + b_rl) * (LDA2 * 2) + (kb + b_co) * 2);
                LDSM2(bl[cb], p);
            }
            #pragma unroll
            for (int rb = 0; rb < 2; rb++)
                #pragma unroll
                for (int cb = 0; cb < 4; cb++)
                    MMA_FP16(acc[rb][cb], ah[rb], bh[cb]);
            #pragma unroll
            for (int rb = 0; rb < 2; rb++)
                #pragma unroll
                for (int cb = 0; cb < 4; cb++)
                    MMA_FP16(acc[rb][cb], ah[rb], bl[cb]);
        }

        #pragma unroll
        for (int rb = 0; rb < 2; rb++) {
            int row = m0 + wm + rb * 16 + (lane >> 2);
            #pragma unroll
            for (int cb = 0; cb < 4; cb++) {
                int col = n0 + wn + cb * 8 + (lane & 3) * 2;
                if (col < V_DIM) {
                    float2 bv = *(const float2*)&Vb[col];
                    float2 o0, o1;
                    o0.x = acc[rb][cb][0] + bv.x; o0.y = acc[rb][cb][1] + bv.y;
                    o1.x = acc[rb][cb][2] + bv.x; o1.y = acc[rb][cb][3] + bv.y;
                    *(float2*)&out[(size_t)row * V_DIM + col] = o0;
                    *(float2*)&out[(size_t)(row + 8) * V_DIM + col] = o1;
                }
            }
        }

        cpa_wait_all();       // prefetch landed (overlapped with compute)
        __syncthreads();
        buf ^= 1;
    }
}

// ---------------- launch ----------------------------------------------------
extern "C" void kernel_launch(void* const* d_in, const int* in_sizes, int n_in,
                              void* d_out, int out_size) {
    const float* x  = (const float*)d_in[0];
    const float* Ww = (const float*)d_in[1];
    const float* Wb = (const float*)d_in[2];
    const float* Uw = (const float*)d_in[3];
    const float* Ub = (const float*)d_in[4];
    const float* Vw = (const float*)d_in[5];
    const float* Vb = (const float*)d_in[6];
    float* out = (float*)d_out;

    cudaFuncSetAttribute(rec_split_kernel,
                         cudaFuncAttributeMaxDynamicSharedMemorySize, REC_SMEM);
    cudaFuncSetAttribute(out_gemm_kernel,
                         cudaFuncAttributeMaxDynamicSharedMemorySize, GEMM_SMEM);

    rec_split_kernel<<<128, 256, REC_SMEM>>>(x, Ww, Wb, Uw, Ub, Vw,
                                             out + OUT_SEQ_ELEMS);
    out_gemm_kernel<<<GRID_GEMM, 256, GEMM_SMEM>>>(Vb, out);
}